// round 10
// baseline (speedup 1.0000x reference)
#include <cuda_runtime.h>
#include <cuda_bf16.h>
#include <math.h>
#include <stdint.h>

#define NN 20000
#define NE 200000

// ---------------- scratch ----------------
__device__ __align__(16) float g_h[NN*64];
__device__ __align__(16) float g_ni[NN*256];
__device__ __align__(16) float g_nj[NN*256];
__device__ __align__(16) float g_hp[NN*256];
__device__ __align__(16) float g_score[(NE+64)*4];   // CSR-position indexed
__device__ int g_rowptr[NN+1];
__device__ int g_cur[NN];
__device__ int g_eidx[NE];
__device__ __align__(16) __nv_bfloat16 g_hb[NN*128];
__device__ __align__(16) __nv_bfloat16 g_fb[NE*128];
__device__ __align__(16) __nv_bfloat16 g_fb2[(NE+64)*128];  // CSR-position ordered f
__device__ __align__(16) __nv_bfloat16 g_wbuf[8*49152];

// ---------------- helpers ----------------
__device__ __forceinline__ uint32_t smem_u32(const void* p){
    uint32_t a;
    asm("{ .reg .u64 t; cvta.to.shared.u64 t, %1; cvt.u32.u64 %0, t; }" : "=r"(a) : "l"(p));
    return a;
}
__device__ __forceinline__ void ldsm4(uint32_t& r0, uint32_t& r1, uint32_t& r2, uint32_t& r3, uint32_t a){
    asm volatile("ldmatrix.sync.aligned.m8n8.x4.shared.b16 {%0,%1,%2,%3}, [%4];"
        : "=r"(r0), "=r"(r1), "=r"(r2), "=r"(r3) : "r"(a));
}
#define MMA16816(d, a0,a1,a2,a3, b0,b1) \
    asm volatile("mma.sync.aligned.m16n8k16.row.col.f32.bf16.bf16.f32 " \
        "{%0,%1,%2,%3}, {%4,%5,%6,%7}, {%8,%9}, {%0,%1,%2,%3};" \
        : "+f"((d)[0]), "+f"((d)[1]), "+f"((d)[2]), "+f"((d)[3]) \
        : "r"(a0), "r"(a1), "r"(a2), "r"(a3), "r"(b0), "r"(b1))
__device__ __forceinline__ float lky(float x){ return x > 0.f ? x : 0.01f*x; }

// ---------------- CSR build ----------------
__global__ void k_count(const int* __restrict__ dst){
    int e = blockIdx.x*blockDim.x + threadIdx.x;
    if (e < NE) atomicAdd(&g_cur[dst[e]], 1);
}
__global__ __launch_bounds__(1024) void k_scan(){
    __shared__ int sPart[1024];
    const int t = threadIdx.x;
    const int beg = t*20;
    const int end = (beg+20 < NN) ? beg+20 : NN;
    int s = 0;
    for (int i=beg; i<end; i++) s += g_cur[i];
    sPart[t] = s;
    __syncthreads();
    for (int o=1; o<1024; o<<=1){
        int v = (t >= o) ? sPart[t-o] : 0;
        __syncthreads();
        sPart[t] += v;
        __syncthreads();
    }
    int run = (t==0) ? 0 : sPart[t-1];
    for (int i=beg; i<end; i++){
        int c = g_cur[i];
        g_rowptr[i] = run;
        g_cur[i]    = run;
        run += c;
    }
    if (t == 0) g_rowptr[NN] = NE;
}
__global__ void k_scatter(const int* __restrict__ dst){
    int e = blockIdx.x*blockDim.x + threadIdx.x;
    if (e < NE){
        int p = atomicAdd(&g_cur[dst[e]], 1);
        g_eidx[p] = e;
    }
}

// ---------------- W' images ----------------
__global__ __launch_bounds__(256) void k_wconv_all(
    const float* __restrict__ Wni, const float* __restrict__ Wnj,
    const float* __restrict__ Wnode, const float* __restrict__ Wfij){
    int idx = blockIdx.x*256 + threadIdx.x;
    if (idx >= 49152) return;
    int m = blockIdx.y;
    int l = m >> 2, which = m & 3;
    const float* W = (which==0?Wni: which==1?Wnj: which==2?Wnode: Wfij) + l*16384;
    int n = idx / 192, kk = idx % 192;
    int ks = kk & 63;
    float v = W[ks*256 + n];
    __nv_bfloat16 h = __float2bfloat16(v);
    if (kk >= 128) h = __float2bfloat16(v - __bfloat162float(h));
    g_wbuf[(size_t)m*49152 + n*192 + kk] = h;
}

// ---------------- node GEMM ----------------
#define MSTR 200
#define MMA_SMEM (2*128*MSTR*2)

__global__ __launch_bounds__(256) void mma_gemm(
    const __nv_bfloat16* __restrict__ ab, const __nv_bfloat16* __restrict__ wimg0,
    const float* __restrict__ bias2,
    float* __restrict__ o0, float* __restrict__ o1, float* __restrict__ o2,
    int rows){
    extern __shared__ __nv_bfloat16 sm[];
    __nv_bfloat16* sA = sm;
    __nv_bfloat16* sW = sm + 128*MSTR;
    const int tid = threadIdx.x;
    const int y = blockIdx.y;
    const int mat = y >> 1;
    const int ch  = y & 1;
    const __nv_bfloat16* wimg = wimg0 + (size_t)mat*49152;
    float* out = (mat==0) ? o0 : (mat==1) ? o1 : o2;
    const float* bias = (mat==2) ? bias2 : nullptr;
    const int row0 = blockIdx.x*128;
    const int cb   = ch*128;

    #pragma unroll
    for (int it=0; it<8; it++){
        int idx = it*256 + tid;
        int r = idx >> 4, c8 = (idx & 15)*8;
        uint4 v = make_uint4(0u,0u,0u,0u);
        if (row0 + r < rows) v = *reinterpret_cast<const uint4*>(ab + (size_t)(row0+r)*128 + c8);
        *reinterpret_cast<uint4*>(sA + r*MSTR + c8) = v;
    }
    #pragma unroll
    for (int it=0; it<4; it++){
        int idx = it*256 + tid;
        int r = idx >> 3, c8 = (idx & 7)*8;
        uint4 v = make_uint4(0u,0u,0u,0u);
        if (row0 + r < rows) v = *reinterpret_cast<const uint4*>(ab + (size_t)(row0+r)*128 + c8);
        *reinterpret_cast<uint4*>(sA + r*MSTR + 128 + c8) = v;
    }
    #pragma unroll
    for (int it=0; it<12; it++){
        int idx = it*256 + tid;
        int n = idx / 24, c8 = (idx % 24)*8;
        uint4 v = *reinterpret_cast<const uint4*>(wimg + (size_t)(cb+n)*192 + c8);
        *reinterpret_cast<uint4*>(sW + n*MSTR + c8) = v;
    }
    __syncthreads();

    const int wid = tid >> 5, lane = tid & 31;
    const int wrow = wid & 1, wcol = wid >> 1;
    const int lr = lane >> 2, lk2 = (lane & 3)*2;
    const uint32_t sAu = smem_u32(sA), sWu = smem_u32(sW);
    const uint32_t arow = (uint32_t)((wrow*64 + (lane & 15))*MSTR + ((lane >> 4) << 3));
    const uint32_t brow = (uint32_t)((wcol*32 + (lane & 7) + ((lane >> 4) << 3))*MSTR + (lane & 8));

    float acc[4][4][4];
    #pragma unroll
    for (int mi=0;mi<4;mi++)
        #pragma unroll
        for (int ni=0;ni<4;ni++)
            #pragma unroll
            for (int q=0;q<4;q++) acc[mi][ni][q] = 0.f;

    #pragma unroll
    for (int ks=0; ks<12; ks++){
        const int k = ks*16;
        uint32_t a[4][4];
        #pragma unroll
        for (int mi=0;mi<4;mi++)
            ldsm4(a[mi][0], a[mi][1], a[mi][2], a[mi][3],
                  sAu + 2u*(arow + (uint32_t)(mi*16*MSTR + k)));
        #pragma unroll
        for (int pr=0; pr<2; pr++){
            uint32_t b0, b1, b2, b3;
            ldsm4(b0, b1, b2, b3, sWu + 2u*(brow + (uint32_t)(pr*16*MSTR + k)));
            #pragma unroll
            for (int mi=0;mi<4;mi++){
                MMA16816(acc[mi][pr*2],   a[mi][0], a[mi][1], a[mi][2], a[mi][3], b0, b1);
                MMA16816(acc[mi][pr*2+1], a[mi][0], a[mi][1], a[mi][2], a[mi][3], b2, b3);
            }
        }
    }

    #pragma unroll
    for (int mi=0;mi<4;mi++){
        #pragma unroll
        for (int ni=0;ni<4;ni++){
            int r = row0 + wrow*64 + mi*16 + lr;
            int c = cb + wcol*32 + ni*8 + lk2;
            float bx = 0.f, by = 0.f;
            if (bias){ bx = bias[c]; by = bias[c+1]; }
            if (r < rows){
                float2 v = make_float2(acc[mi][ni][0] + bx, acc[mi][ni][1] + by);
                *reinterpret_cast<float2*>(out + (size_t)r*256 + c) = v;
            }
            if (r + 8 < rows){
                float2 v = make_float2(acc[mi][ni][2] + bx, acc[mi][ni][3] + by);
                *reinterpret_cast<float2*>(out + (size_t)(r+8)*256 + c) = v;
            }
        }
    }
}

// ---------------- edge GEMM v4: CSR-ordered edges, single-shot K=192, fused epilogue ----------------
#define EASTR 200
#define FOS  260
#define EG_EID 153600                 // byte offset of sEid (past sA+sW)
#define EG_SMEM (153600 + 1024)

__global__ __launch_bounds__(512) void edge_gemm(
    const __nv_bfloat16* __restrict__ wimg,
    const __nv_bfloat16* __restrict__ fin,   // input f: by edge id (csr_in=0) or by position (csr_in=1)
    __nv_bfloat16* __restrict__ fout,        // output f: by CSR position
    const int* __restrict__ src, const int* __restrict__ dst,
    const float* __restrict__ bias_e, const float* __restrict__ attn,
    int csr_in){
    extern __shared__ __nv_bfloat16 sm[];
    __nv_bfloat16* sA = sm;                   // [128][EASTR], 192 cols used
    __nv_bfloat16* sW = sm + 128*EASTR;       // [256][EASTR], 192 cols used
    int* sEid = reinterpret_cast<int*>(reinterpret_cast<char*>(sm) + EG_EID);
    int* sDst = sEid + 128;
    const int tid = threadIdx.x;
    const int e0 = blockIdx.x*128;            // CSR position base

    if (tid < 128){
        int pos = e0 + tid;
        int e = g_eidx[(pos < NE) ? pos : 0];
        sEid[tid] = e;
        sDst[tid] = dst[e];
    }
    // W load (independent of sEid)
    #pragma unroll
    for (int it=0; it<12; it++){
        int idx = it*512 + tid;               // 6144 uint4
        int n = idx / 24, c8 = idx - n*24;
        uint4 v = *reinterpret_cast<const uint4*>(wimg + (size_t)n*192 + c8*8);
        *reinterpret_cast<uint4*>(sW + n*EASTR + c8*8) = v;
    }
    __syncthreads();
    // A load: 128 rows x 192 cols = 3072 uint4; cols [0..127]=fin row, [128..191]=hi replica
    #pragma unroll
    for (int it=0; it<6; it++){
        int idx = it*512 + tid;
        int r = idx / 24, c8 = idx - r*24;
        int fc8 = (c8 < 16) ? c8 : (c8 - 16);
        const __nv_bfloat16* ap = csr_in
            ? fin + (size_t)((e0 + r < NE) ? (e0 + r) : (NE-1))*128
            : fin + (size_t)sEid[r]*128;
        uint4 v = *reinterpret_cast<const uint4*>(ap + fc8*8);
        *reinterpret_cast<uint4*>(sA + r*EASTR + c8*8) = v;
    }
    __syncthreads();

    const int wid = tid >> 5, lane = tid & 31;
    const int wrow = wid & 3, wcol = wid >> 2;   // warp tile m32 x n64 (16 warps)
    const int lr = lane >> 2, lk2 = (lane & 3)*2;
    const uint32_t sAu = smem_u32(sA), sWu = smem_u32(sW);
    const uint32_t arow = (uint32_t)((wrow*32 + (lane & 15))*EASTR + ((lane >> 4) << 3));
    const uint32_t brow = (uint32_t)((wcol*64 + (lane & 7) + ((lane >> 4) << 3))*EASTR + (lane & 8));

    float acc[2][8][4];
    #pragma unroll
    for (int mi=0;mi<2;mi++)
        #pragma unroll
        for (int n8=0;n8<8;n8++)
            #pragma unroll
            for (int q=0;q<4;q++) acc[mi][n8][q] = 0.f;

    #pragma unroll
    for (int ks=0; ks<12; ks++){
        const int k = ks*16;
        uint32_t a[2][4];
        #pragma unroll
        for (int mi=0;mi<2;mi++)
            ldsm4(a[mi][0], a[mi][1], a[mi][2], a[mi][3],
                  sAu + 2u*(arow + (uint32_t)(mi*16*EASTR + k)));
        #pragma unroll
        for (int nb=0; nb<4; nb++){
            uint32_t b0, b1, b2, b3;
            ldsm4(b0, b1, b2, b3, sWu + 2u*(brow + (uint32_t)(nb*16*EASTR + k)));
            #pragma unroll
            for (int mi=0;mi<2;mi++){
                MMA16816(acc[mi][nb*2],   a[mi][0], a[mi][1], a[mi][2], a[mi][3], b0, b1);
                MMA16816(acc[mi][nb*2+1], a[mi][0], a[mi][1], a[mi][2], a[mi][3], b2, b3);
            }
        }
    }
    __syncthreads();

    // spill fo (pre-bias) into sFo [128][FOS] (overlays sA/sW; sEid/sDst live above)
    float* sFo = reinterpret_cast<float*>(sm);
    #pragma unroll
    for (int mi=0;mi<2;mi++){
        int rl = wrow*32 + mi*16 + lr;
        #pragma unroll
        for (int n8=0;n8<8;n8++){
            int c = wcol*64 + n8*8 + lk2;
            sFo[rl*FOS + c]         = acc[mi][n8][0];
            sFo[rl*FOS + c + 1]     = acc[mi][n8][1];
            sFo[(rl+8)*FOS + c]     = acc[mi][n8][2];
            sFo[(rl+8)*FOS + c + 1] = acc[mi][n8][3];
        }
    }
    __syncthreads();

    // epilogue: warp-per-edge (CSR order), 8 edges per warp, one-ahead gather pipeline
    const int c1 = lane*4, c2 = 128 + lane*4;
    const float4 be1 = *reinterpret_cast<const float4*>(bias_e + c1);
    const float4 be2 = *reinterpret_cast<const float4*>(bias_e + c2);
    const float4 at1 = *reinterpret_cast<const float4*>(attn + c1);
    const float4 at2 = *reinterpret_cast<const float4*>(attn + c2);

    float4 n1c, n2c, j1c, j2c;
    {
        int el = wid*8;
        int s = src[sEid[el]], d = sDst[el];
        n1c = *reinterpret_cast<const float4*>(g_ni + (size_t)s*256 + c1);
        n2c = *reinterpret_cast<const float4*>(g_ni + (size_t)s*256 + c2);
        j1c = *reinterpret_cast<const float4*>(g_nj + (size_t)d*256 + c1);
        j2c = *reinterpret_cast<const float4*>(g_nj + (size_t)d*256 + c2);
    }

    #pragma unroll 1
    for (int it=0; it<8; it++){
        const int el  = wid*8 + it;
        const int pos = e0 + el;
        const bool valid = (pos < NE);
        float4 n1 = n1c, n2 = n2c, j1 = j1c, j2 = j2c;
        if (it < 7){
            int el2 = el + 1;
            int s2 = src[sEid[el2]], d2 = sDst[el2];
            n1c = *reinterpret_cast<const float4*>(g_ni + (size_t)s2*256 + c1);
            n2c = *reinterpret_cast<const float4*>(g_ni + (size_t)s2*256 + c2);
            j1c = *reinterpret_cast<const float4*>(g_nj + (size_t)d2*256 + c1);
            j2c = *reinterpret_cast<const float4*>(g_nj + (size_t)d2*256 + c2);
        }
        float4 f1 = *reinterpret_cast<const float4*>(sFo + el*FOS + c1);
        float4 f2 = *reinterpret_cast<const float4*>(sFo + el*FOS + c2);
        f1.x += be1.x + n1.x + j1.x; f1.y += be1.y + n1.y + j1.y;
        f1.z += be1.z + n1.z + j1.z; f1.w += be1.w + n1.w + j1.w;
        f2.x += be2.x + n2.x + j2.x; f2.y += be2.y + n2.y + j2.y;
        f2.z += be2.z + n2.z + j2.z; f2.w += be2.w + n2.w + j2.w;

        float p1 = lky(f1.x)*at1.x + lky(f1.y)*at1.y + lky(f1.z)*at1.z + lky(f1.w)*at1.w;
        float p2 = lky(f2.x)*at2.x + lky(f2.y)*at2.y + lky(f2.z)*at2.z + lky(f2.w)*at2.w;
        #pragma unroll
        for (int o=8;o>0;o>>=1){
            p1 += __shfl_xor_sync(0xffffffffu, p1, o);
            p2 += __shfl_xor_sync(0xffffffffu, p2, o);
        }
        if (valid){
            if (lane == 0){
                g_score[(size_t)pos*4 + 0] = p1;
                g_score[(size_t)pos*4 + 2] = p2;
            } else if (lane == 16){
                g_score[(size_t)pos*4 + 1] = p1;
                g_score[(size_t)pos*4 + 3] = p2;
            }
        }

        float4 hm;
        hm.x = f1.x + f2.x; hm.y = f1.y + f2.y; hm.z = f1.z + f2.z; hm.w = f1.w + f2.w;
        hm.x = 0.25f*(hm.x + __shfl_xor_sync(0xffffffffu, hm.x, 16));
        hm.y = 0.25f*(hm.y + __shfl_xor_sync(0xffffffffu, hm.y, 16));
        hm.z = 0.25f*(hm.z + __shfl_xor_sync(0xffffffffu, hm.z, 16));
        hm.w = 0.25f*(hm.w + __shfl_xor_sync(0xffffffffu, hm.w, 16));
        float s1 = hm.x + hm.y + hm.z + hm.w;
        float s2 = hm.x*hm.x + hm.y*hm.y + hm.z*hm.z + hm.w*hm.w;
        #pragma unroll
        for (int o=8;o>0;o>>=1){
            s1 += __shfl_xor_sync(0xffffffffu, s1, o);
            s2 += __shfl_xor_sync(0xffffffffu, s2, o);
        }
        float m   = s1 * 0.015625f;
        float var = s2 * 0.015625f - m*m;
        float inv = rsqrtf(var + 1e-5f);
        if (valid && lane < 16){
            float4 o4;
            o4.x = (hm.x - m)*inv; o4.x = o4.x > 0.f ? o4.x : expm1f(o4.x);
            o4.y = (hm.y - m)*inv; o4.y = o4.y > 0.f ? o4.y : expm1f(o4.y);
            o4.z = (hm.z - m)*inv; o4.z = o4.z > 0.f ? o4.z : expm1f(o4.z);
            o4.w = (hm.w - m)*inv; o4.w = o4.w > 0.f ? o4.w : expm1f(o4.w);
            __nv_bfloat16 h0 = __float2bfloat16(o4.x), h1 = __float2bfloat16(o4.y);
            __nv_bfloat16 h2 = __float2bfloat16(o4.z), h3 = __float2bfloat16(o4.w);
            __nv_bfloat16 l0 = __float2bfloat16(o4.x - __bfloat162float(h0));
            __nv_bfloat16 l1 = __float2bfloat16(o4.y - __bfloat162float(h1));
            __nv_bfloat16 l2 = __float2bfloat16(o4.z - __bfloat162float(h2));
            __nv_bfloat16 l3 = __float2bfloat16(o4.w - __bfloat162float(h3));
            int t = c1;
            __nv_bfloat162* dh = reinterpret_cast<__nv_bfloat162*>(fout + (size_t)pos*128 + t);
            dh[0] = __nv_bfloat162(h0, h1);
            dh[1] = __nv_bfloat162(h2, h3);
            __nv_bfloat162* dl = reinterpret_cast<__nv_bfloat162*>(fout + (size_t)pos*128 + 64 + t);
            dl[0] = __nv_bfloat162(l0, l1);
            dl[1] = __nv_bfloat162(l2, l3);
        }
    }
}

// ---------------- small GEMMs ----------------
__global__ __launch_bounds__(256) void sg_init(
    const float* __restrict__ A0, const float* __restrict__ W0, const float* __restrict__ b0,
    const float* __restrict__ A1, const float* __restrict__ W1, const float* __restrict__ b1){
    const int y = blockIdx.y;
    const float* A = y ? A1 : A0;
    const float* W = y ? W1 : W0;
    const float* bias = y ? b1 : b0;
    __nv_bfloat16* out2 = y ? g_fb : g_hb;
    const int rows = y ? NE : NN;
    const int K    = y ? 15 : 65;
    __shared__ float sW[65*64];
    __shared__ float sA[4*65];
    for (int i=threadIdx.x; i<K*64; i+=256) sW[i] = W[i];
    __syncthreads();
    const int col = threadIdx.x & 63;
    const int rl  = threadIdx.x >> 6;
    const float b = bias[col];
    for (int base = blockIdx.x*4; base < rows; base += gridDim.x*4){
        for (int i=threadIdx.x; i<4*K; i+=256){
            int r = i / K, k = i - r*K;
            sA[i] = (base + r < rows) ? A[(size_t)(base+r)*K + k] : 0.f;
        }
        __syncthreads();
        const int row = base + rl;
        if (row < rows){
            float acc = b;
            for (int k=0;k<K;k++) acc += sA[rl*K + k]*sW[k*64 + col];
            __nv_bfloat16 h = __float2bfloat16(acc);
            out2[(size_t)row*128 + col]      = h;
            out2[(size_t)row*128 + 64 + col] = __float2bfloat16(acc - __bfloat162float(h));
        }
        __syncthreads();
    }
}

__global__ __launch_bounds__(256) void sg_final(
    const float* __restrict__ W, const float* __restrict__ bias, float* __restrict__ out){
    __shared__ float sW[64*64];
    __shared__ float sA[4*64];
    for (int i=threadIdx.x; i<64*64; i+=256) sW[i] = W[i];
    __syncthreads();
    const int col = threadIdx.x & 63;
    const int rl  = threadIdx.x >> 6;
    const float b = bias[col];
    for (int base = blockIdx.x*4; base < NN; base += gridDim.x*4){
        for (int i=threadIdx.x; i<4*64; i+=256){
            int r = i >> 6, k = i & 63;
            sA[i] = (base + r < NN) ? g_h[(base+r)*64 + k] : 0.f;
        }
        __syncthreads();
        const int row = base + rl;
        if (row < NN){
            float acc = b;
            for (int k=0;k<64;k++) acc += sA[rl*64 + k]*sW[k*64 + col];
            out[row*64 + col] = acc;
        }
        __syncthreads();
    }
}

// ---------------- fused softmax + aggregate (scores now CSR-position contiguous) ----------------
__global__ __launch_bounds__(256) void aggregate(const int* __restrict__ src){
    const int g = threadIdx.x >> 6;
    const int t = threadIdx.x & 63;
    const int n = blockIdx.x*4 + g;
    const int wlocal = (t >> 5);
    const int lane = threadIdx.x & 31;
    const int beg = g_rowptr[n], end = g_rowptr[n+1];
    const float4* SC = reinterpret_cast<const float4*>(g_score);

    float4 mx = make_float4(-3.4e38f,-3.4e38f,-3.4e38f,-3.4e38f);
    for (int i=beg+t; i<end; i+=64){
        float4 s = SC[i];
        mx.x = fmaxf(mx.x, s.x); mx.y = fmaxf(mx.y, s.y);
        mx.z = fmaxf(mx.z, s.z); mx.w = fmaxf(mx.w, s.w);
    }
    #pragma unroll
    for (int o=16;o>0;o>>=1){
        mx.x = fmaxf(mx.x, __shfl_down_sync(0xffffffffu, mx.x, o));
        mx.y = fmaxf(mx.y, __shfl_down_sync(0xffffffffu, mx.y, o));
        mx.z = fmaxf(mx.z, __shfl_down_sync(0xffffffffu, mx.z, o));
        mx.w = fmaxf(mx.w, __shfl_down_sync(0xffffffffu, mx.w, o));
    }
    __shared__ float4 sM[4][2];
    __shared__ float4 sD[4][2];
    if (lane == 0) sM[g][wlocal] = mx;
    __syncthreads();
    mx.x = fmaxf(sM[g][0].x, sM[g][1].x); mx.y = fmaxf(sM[g][0].y, sM[g][1].y);
    mx.z = fmaxf(sM[g][0].z, sM[g][1].z); mx.w = fmaxf(sM[g][0].w, sM[g][1].w);

    float4 dn = make_float4(0.f,0.f,0.f,0.f);
    for (int i=beg+t; i<end; i+=64){
        float4 s = SC[i];
        dn.x += __expf(s.x-mx.x); dn.y += __expf(s.y-mx.y);
        dn.z += __expf(s.z-mx.z); dn.w += __expf(s.w-mx.w);
    }
    #pragma unroll
    for (int o=16;o>0;o>>=1){
        dn.x += __shfl_down_sync(0xffffffffu, dn.x, o);
        dn.y += __shfl_down_sync(0xffffffffu, dn.y, o);
        dn.z += __shfl_down_sync(0xffffffffu, dn.z, o);
        dn.w += __shfl_down_sync(0xffffffffu, dn.w, o);
    }
    if (lane == 0) sD[g][wlocal] = dn;
    __syncthreads();
    dn.x = sD[g][0].x + sD[g][1].x; dn.y = sD[g][0].y + sD[g][1].y;
    dn.z = sD[g][0].z + sD[g][1].z; dn.w = sD[g][0].w + sD[g][1].w;

    const int q = t >> 4;
    const float mq = (q==0)?mx.x:(q==1)?mx.y:(q==2)?mx.z:mx.w;
    const float dq = (q==0)?dn.x:(q==1)?dn.y:(q==2)?dn.z:dn.w;
    const float rq = (end > beg) ? 1.0f/dq : 0.f;
    float4 acc = make_float4(0.f,0.f,0.f,0.f);
    for (int i=beg; i<end; i++){
        int e = g_eidx[i];
        float a = __expf(g_score[(size_t)i*4 + q] - mq) * rq;
        float4 hp = reinterpret_cast<const float4*>(g_hp)[src[e]*64 + t];
        acc.x += hp.x*a; acc.y += hp.y*a; acc.z += hp.z*a; acc.w += hp.w*a;
    }

    __shared__ float sAcc[4][256];
    reinterpret_cast<float4*>(&sAcc[g][0])[t] = acc;
    __syncthreads();
    float v = 0.25f*(sAcc[g][t] + sAcc[g][t+64] + sAcc[g][t+128] + sAcc[g][t+192]);
    float s1 = v, s2 = v*v;
    #pragma unroll
    for (int o=16;o>0;o>>=1){
        s1 += __shfl_down_sync(0xffffffffu, s1, o);
        s2 += __shfl_down_sync(0xffffffffu, s2, o);
    }
    __shared__ float sS[4][4];
    if (lane == 0){ sS[g][wlocal] = s1; sS[g][2+wlocal] = s2; }
    __syncthreads();
    float m   = (sS[g][0]+sS[g][1]) * 0.015625f;
    float var = (sS[g][2]+sS[g][3]) * 0.015625f - m*m;
    float o = (v - m) * rsqrtf(var + 1e-5f);
    o = o > 0.f ? o : expm1f(o);
    g_h[n*64 + t] = o;
    __nv_bfloat16 hi = __float2bfloat16(o);
    g_hb[(size_t)n*128 + t]      = hi;
    g_hb[(size_t)n*128 + 64 + t] = __float2bfloat16(o - __bfloat162float(hi));
}

// ---------------- host ----------------
extern "C" void kernel_launch(void* const* d_in, const int* in_sizes, int n_in,
                              void* d_out, int out_size){
    (void)in_sizes; (void)n_in; (void)out_size;
    const float* x      = (const float*)d_in[0];
    const float* efeat  = (const float*)d_in[1];
    const int*   src    = (const int*)  d_in[2];
    const int*   dst    = (const int*)  d_in[3];
    const float* Wn0    = (const float*)d_in[4];
    const float* bn0    = (const float*)d_in[5];
    const float* We0    = (const float*)d_in[6];
    const float* be0    = (const float*)d_in[7];
    const float* Wnode  = (const float*)d_in[8];
    const float* bnode  = (const float*)d_in[9];
    const float* Wni    = (const float*)d_in[10];
    const float* Wnj    = (const float*)d_in[11];
    const float* Wfij   = (const float*)d_in[12];
    const float* attn   = (const float*)d_in[13];
    const float* bias_e = (const float*)d_in[14];
    const float* Wf     = (const float*)d_in[15];
    const float* bf     = (const float*)d_in[16];

    float *p_ni, *p_nj, *p_hp;
    __nv_bfloat16 *p_hb, *p_fb, *p_fb2, *p_wb;
    int* p_cur;
    cudaGetSymbolAddress((void**)&p_ni, g_ni);
    cudaGetSymbolAddress((void**)&p_nj, g_nj);
    cudaGetSymbolAddress((void**)&p_hp, g_hp);
    cudaGetSymbolAddress((void**)&p_hb, g_hb);
    cudaGetSymbolAddress((void**)&p_fb, g_fb);
    cudaGetSymbolAddress((void**)&p_fb2, g_fb2);
    cudaGetSymbolAddress((void**)&p_wb, g_wbuf);
    cudaGetSymbolAddress((void**)&p_cur, g_cur);

    cudaFuncSetAttribute(mma_gemm,  cudaFuncAttributeMaxDynamicSharedMemorySize, MMA_SMEM);
    cudaFuncSetAttribute(edge_gemm, cudaFuncAttributeMaxDynamicSharedMemorySize, EG_SMEM);

    sg_init<<<dim3(8192, 2), 256>>>(x, Wn0, bn0, efeat, We0, be0);        // 0
    k_wconv_all<<<dim3(192, 8), 256>>>(Wni, Wnj, Wnode, Wfij);            // 1
    cudaMemsetAsync(p_cur, 0, NN*sizeof(int));
    k_count<<<(NE+255)/256, 256>>>(dst);                                  // 2
    mma_gemm<<<dim3(157, 6), 256, MMA_SMEM>>>(
        p_hb, p_wb, bnode, p_ni, p_nj, p_hp, NN);                         // 3  <-- profiled
    k_scan<<<1, 1024>>>();                                                // 4
    k_scatter<<<(NE+255)/256, 256>>>(dst);                                // 5
    edge_gemm<<<1563, 512, EG_SMEM>>>(
        p_wb + (size_t)3*49152, p_fb, p_fb2, src, dst, bias_e, attn, 0);  // 6
    aggregate<<<NN/4, 256>>>(src);                                        // 7

    mma_gemm<<<dim3(157, 6), 256, MMA_SMEM>>>(
        p_hb, p_wb + (size_t)4*49152, bnode + 256, p_ni, p_nj, p_hp, NN); // 8
    edge_gemm<<<1563, 512, EG_SMEM>>>(
        p_wb + (size_t)7*49152, p_fb2, p_fb, src, dst, bias_e + 256, attn + 256, 1); // 9
    aggregate<<<NN/4, 256>>>(src);                                        // 10

    sg_final<<<5000, 256>>>(Wf, bf, (float*)d_out);                       // 11
}

// round 15
// speedup vs baseline: 1.1605x; 1.1605x over previous
#include <cuda_runtime.h>
#include <cuda_bf16.h>
#include <math.h>
#include <stdint.h>

#define NN 20000
#define NE 200000

// ---------------- scratch ----------------
__device__ __align__(16) float g_h[NN*64];
__device__ __align__(16) float g_ni[NN*256];
__device__ __align__(16) float g_nj[NN*256];
__device__ __align__(16) float g_hp[NN*256];
__device__ __align__(16) float g_score[NE*4];
__device__ int g_rowptr[NN+1];
__device__ int g_cur[NN];
__device__ int g_eidx[NE];
__device__ __align__(16) __nv_bfloat16 g_hb[NN*128];
__device__ __align__(16) __nv_bfloat16 g_fb[NE*128];
__device__ __align__(16) __nv_bfloat16 g_wbuf[8*49152];

// ---------------- helpers ----------------
__device__ __forceinline__ uint32_t smem_u32(const void* p){
    uint32_t a;
    asm("{ .reg .u64 t; cvta.to.shared.u64 t, %1; cvt.u32.u64 %0, t; }" : "=r"(a) : "l"(p));
    return a;
}
__device__ __forceinline__ void ldsm4(uint32_t& r0, uint32_t& r1, uint32_t& r2, uint32_t& r3, uint32_t a){
    asm volatile("ldmatrix.sync.aligned.m8n8.x4.shared.b16 {%0,%1,%2,%3}, [%4];"
        : "=r"(r0), "=r"(r1), "=r"(r2), "=r"(r3) : "r"(a));
}
#define MMA16816(d, a0,a1,a2,a3, b0,b1) \
    asm volatile("mma.sync.aligned.m16n8k16.row.col.f32.bf16.bf16.f32 " \
        "{%0,%1,%2,%3}, {%4,%5,%6,%7}, {%8,%9}, {%0,%1,%2,%3};" \
        : "+f"((d)[0]), "+f"((d)[1]), "+f"((d)[2]), "+f"((d)[3]) \
        : "r"(a0), "r"(a1), "r"(a2), "r"(a3), "r"(b0), "r"(b1))
__device__ __forceinline__ float lky(float x){ return x > 0.f ? x : 0.01f*x; }

// ---------------- CSR build ----------------
__global__ void k_count(const int* __restrict__ dst){
    int e = blockIdx.x*blockDim.x + threadIdx.x;
    if (e < NE) atomicAdd(&g_cur[dst[e]], 1);
}
__global__ __launch_bounds__(1024) void k_scan(){
    __shared__ int sPart[1024];
    const int t = threadIdx.x;
    const int beg = t*20;
    const int end = (beg+20 < NN) ? beg+20 : NN;
    int s = 0;
    for (int i=beg; i<end; i++) s += g_cur[i];
    sPart[t] = s;
    __syncthreads();
    for (int o=1; o<1024; o<<=1){
        int v = (t >= o) ? sPart[t-o] : 0;
        __syncthreads();
        sPart[t] += v;
        __syncthreads();
    }
    int run = (t==0) ? 0 : sPart[t-1];
    for (int i=beg; i<end; i++){
        int c = g_cur[i];
        g_rowptr[i] = run;
        g_cur[i]    = run;
        run += c;
    }
    if (t == 0) g_rowptr[NN] = NE;
}
__global__ void k_scatter(const int* __restrict__ dst){
    int e = blockIdx.x*blockDim.x + threadIdx.x;
    if (e < NE){
        int p = atomicAdd(&g_cur[dst[e]], 1);
        g_eidx[p] = e;
    }
}

// ---------------- W' images ----------------
__global__ __launch_bounds__(256) void k_wconv_all(
    const float* __restrict__ Wni, const float* __restrict__ Wnj,
    const float* __restrict__ Wnode, const float* __restrict__ Wfij){
    int idx = blockIdx.x*256 + threadIdx.x;
    if (idx >= 49152) return;
    int m = blockIdx.y;
    int l = m >> 2, which = m & 3;
    const float* W = (which==0?Wni: which==1?Wnj: which==2?Wnode: Wfij) + l*16384;
    int n = idx / 192, kk = idx % 192;
    int ks = kk & 63;
    float v = W[ks*256 + n];
    __nv_bfloat16 h = __float2bfloat16(v);
    if (kk >= 128) h = __float2bfloat16(v - __bfloat162float(h));
    g_wbuf[(size_t)m*49152 + n*192 + kk] = h;
}

// ---------------- node GEMM ----------------
#define MSTR 200
#define MMA_SMEM (2*128*MSTR*2)

__global__ __launch_bounds__(256) void mma_gemm(
    const __nv_bfloat16* __restrict__ ab, const __nv_bfloat16* __restrict__ wimg0,
    const float* __restrict__ bias2,
    float* __restrict__ o0, float* __restrict__ o1, float* __restrict__ o2,
    int rows){
    extern __shared__ __nv_bfloat16 sm[];
    __nv_bfloat16* sA = sm;
    __nv_bfloat16* sW = sm + 128*MSTR;
    const int tid = threadIdx.x;
    const int y = blockIdx.y;
    const int mat = y >> 1;
    const int ch  = y & 1;
    const __nv_bfloat16* wimg = wimg0 + (size_t)mat*49152;
    float* out = (mat==0) ? o0 : (mat==1) ? o1 : o2;
    const float* bias = (mat==2) ? bias2 : nullptr;
    const int row0 = blockIdx.x*128;
    const int cb   = ch*128;

    #pragma unroll
    for (int it=0; it<8; it++){
        int idx = it*256 + tid;
        int r = idx >> 4, c8 = (idx & 15)*8;
        uint4 v = make_uint4(0u,0u,0u,0u);
        if (row0 + r < rows) v = *reinterpret_cast<const uint4*>(ab + (size_t)(row0+r)*128 + c8);
        *reinterpret_cast<uint4*>(sA + r*MSTR + c8) = v;
    }
    #pragma unroll
    for (int it=0; it<4; it++){
        int idx = it*256 + tid;
        int r = idx >> 3, c8 = (idx & 7)*8;
        uint4 v = make_uint4(0u,0u,0u,0u);
        if (row0 + r < rows) v = *reinterpret_cast<const uint4*>(ab + (size_t)(row0+r)*128 + c8);
        *reinterpret_cast<uint4*>(sA + r*MSTR + 128 + c8) = v;
    }
    #pragma unroll
    for (int it=0; it<12; it++){
        int idx = it*256 + tid;
        int n = idx / 24, c8 = (idx % 24)*8;
        uint4 v = *reinterpret_cast<const uint4*>(wimg + (size_t)(cb+n)*192 + c8);
        *reinterpret_cast<uint4*>(sW + n*MSTR + c8) = v;
    }
    __syncthreads();

    const int wid = tid >> 5, lane = tid & 31;
    const int wrow = wid & 1, wcol = wid >> 1;
    const int lr = lane >> 2, lk2 = (lane & 3)*2;
    const uint32_t sAu = smem_u32(sA), sWu = smem_u32(sW);
    const uint32_t arow = (uint32_t)((wrow*64 + (lane & 15))*MSTR + ((lane >> 4) << 3));
    const uint32_t brow = (uint32_t)((wcol*32 + (lane & 7) + ((lane >> 4) << 3))*MSTR + (lane & 8));

    float acc[4][4][4];
    #pragma unroll
    for (int mi=0;mi<4;mi++)
        #pragma unroll
        for (int ni=0;ni<4;ni++)
            #pragma unroll
            for (int q=0;q<4;q++) acc[mi][ni][q] = 0.f;

    #pragma unroll
    for (int ks=0; ks<12; ks++){
        const int k = ks*16;
        uint32_t a[4][4];
        #pragma unroll
        for (int mi=0;mi<4;mi++)
            ldsm4(a[mi][0], a[mi][1], a[mi][2], a[mi][3],
                  sAu + 2u*(arow + (uint32_t)(mi*16*MSTR + k)));
        #pragma unroll
        for (int pr=0; pr<2; pr++){
            uint32_t b0, b1, b2, b3;
            ldsm4(b0, b1, b2, b3, sWu + 2u*(brow + (uint32_t)(pr*16*MSTR + k)));
            #pragma unroll
            for (int mi=0;mi<4;mi++){
                MMA16816(acc[mi][pr*2],   a[mi][0], a[mi][1], a[mi][2], a[mi][3], b0, b1);
                MMA16816(acc[mi][pr*2+1], a[mi][0], a[mi][1], a[mi][2], a[mi][3], b2, b3);
            }
        }
    }

    #pragma unroll
    for (int mi=0;mi<4;mi++){
        #pragma unroll
        for (int ni=0;ni<4;ni++){
            int r = row0 + wrow*64 + mi*16 + lr;
            int c = cb + wcol*32 + ni*8 + lk2;
            float bx = 0.f, by = 0.f;
            if (bias){ bx = bias[c]; by = bias[c+1]; }
            if (r < rows){
                float2 v = make_float2(acc[mi][ni][0] + bx, acc[mi][ni][1] + by);
                *reinterpret_cast<float2*>(out + (size_t)r*256 + c) = v;
            }
            if (r + 8 < rows){
                float2 v = make_float2(acc[mi][ni][2] + bx, acc[mi][ni][3] + by);
                *reinterpret_cast<float2*>(out + (size_t)(r+8)*256 + c) = v;
            }
        }
    }
}

// ---------------- edge GEMM v5: 64-edge tile, 256 threads, 2 CTAs/SM, fused epilogue ----------------
#define ASTR 104
#define FOS  260
#define EG_SMEM 66560   // max(64*104*2 + 256*104*2, 64*260*4) = 66560

__global__ void __launch_bounds__(256, 2) edge_gemm(
    const __nv_bfloat16* __restrict__ wimg,
    const int* __restrict__ src, const int* __restrict__ dst,
    const float* __restrict__ bias_e, const float* __restrict__ attn){
    extern __shared__ __nv_bfloat16 sm[];
    __nv_bfloat16* sA = sm;                  // [64][ASTR], 96 k used
    __nv_bfloat16* sW = sm + 64*ASTR;        // [256][ASTR], 96 k used
    const int tid = threadIdx.x;
    const int e0 = blockIdx.x*64;            // NE = 64*3125 exactly, no tails
    const int wid = tid >> 5, lane = tid & 31;
    const int wrow = wid & 1, wcol = wid >> 1;   // warp tile m32 x n64
    const int lr = lane >> 2, lk2 = (lane & 3)*2;
    const uint32_t sAu = smem_u32(sA), sWu = smem_u32(sW);
    const uint32_t arow = (uint32_t)((wrow*32 + (lane & 15))*ASTR + ((lane >> 4) << 3));
    const uint32_t brow = (uint32_t)((wcol*64 + (lane & 7) + ((lane >> 4) << 3))*ASTR + (lane & 8));

    float acc[2][8][4];
    #pragma unroll
    for (int mi=0;mi<2;mi++)
        #pragma unroll
        for (int n8=0;n8<8;n8++)
            #pragma unroll
            for (int q=0;q<4;q++) acc[mi][n8][q] = 0.f;

    #pragma unroll 1
    for (int ck=0; ck<2; ck++){
        __syncthreads();
        // A: 64 rows x 96 cols = 768 uint4; chunk1 cols = fb[96..127] then fb[0..63]
        #pragma unroll
        for (int it=0; it<3; it++){
            int idx = it*256 + tid;
            int r = idx / 12, c8 = idx - r*12;
            int fc8 = (ck == 0) ? c8 : ((c8 < 4) ? 12 + c8 : c8 - 4);
            uint4 v = *reinterpret_cast<const uint4*>(g_fb + (size_t)(e0+r)*128 + fc8*8);
            *reinterpret_cast<uint4*>(sA + r*ASTR + c8*8) = v;
        }
        // W: 256 rows x 96 cols = 3072 uint4
        #pragma unroll
        for (int it=0; it<12; it++){
            int idx = it*256 + tid;
            int n = idx / 12, c8 = idx - n*12;
            uint4 v = *reinterpret_cast<const uint4*>(wimg + (size_t)n*192 + ck*96 + c8*8);
            *reinterpret_cast<uint4*>(sW + n*ASTR + c8*8) = v;
        }
        __syncthreads();

        #pragma unroll
        for (int ks=0; ks<6; ks++){
            const int k = ks*16;
            uint32_t a[2][4];
            #pragma unroll
            for (int mi=0;mi<2;mi++)
                ldsm4(a[mi][0], a[mi][1], a[mi][2], a[mi][3],
                      sAu + 2u*(arow + (uint32_t)(mi*16*ASTR + k)));
            #pragma unroll
            for (int nb=0; nb<4; nb++){
                uint32_t b0, b1, b2, b3;
                ldsm4(b0, b1, b2, b3, sWu + 2u*(brow + (uint32_t)(nb*16*ASTR + k)));
                #pragma unroll
                for (int mi=0;mi<2;mi++){
                    MMA16816(acc[mi][nb*2],   a[mi][0], a[mi][1], a[mi][2], a[mi][3], b0, b1);
                    MMA16816(acc[mi][nb*2+1], a[mi][0], a[mi][1], a[mi][2], a[mi][3], b2, b3);
                }
            }
        }
    }
    __syncthreads();

    // spill fo (pre-bias) into sFo [64][FOS]
    float* sFo = reinterpret_cast<float*>(sm);
    #pragma unroll
    for (int mi=0;mi<2;mi++){
        int rl = wrow*32 + mi*16 + lr;
        #pragma unroll
        for (int n8=0;n8<8;n8++){
            int c = wcol*64 + n8*8 + lk2;
            sFo[rl*FOS + c]         = acc[mi][n8][0];
            sFo[rl*FOS + c + 1]     = acc[mi][n8][1];
            sFo[(rl+8)*FOS + c]     = acc[mi][n8][2];
            sFo[(rl+8)*FOS + c + 1] = acc[mi][n8][3];
        }
    }
    __syncthreads();

    // epilogue: warp-per-edge, 8 edges per warp, one-ahead gather pipeline
    const int c1 = lane*4, c2 = 128 + lane*4;
    const float4 be1 = *reinterpret_cast<const float4*>(bias_e + c1);
    const float4 be2 = *reinterpret_cast<const float4*>(bias_e + c2);
    const float4 at1 = *reinterpret_cast<const float4*>(attn + c1);
    const float4 at2 = *reinterpret_cast<const float4*>(attn + c2);

    float4 n1c, n2c, j1c, j2c;
    {
        int e = e0 + wid*8;
        int s = src[e], d = dst[e];
        n1c = *reinterpret_cast<const float4*>(g_ni + (size_t)s*256 + c1);
        n2c = *reinterpret_cast<const float4*>(g_ni + (size_t)s*256 + c2);
        j1c = *reinterpret_cast<const float4*>(g_nj + (size_t)d*256 + c1);
        j2c = *reinterpret_cast<const float4*>(g_nj + (size_t)d*256 + c2);
    }

    #pragma unroll 1
    for (int it=0; it<8; it++){
        const int el = wid*8 + it;
        const int e  = e0 + el;
        float4 n1 = n1c, n2 = n2c, j1 = j1c, j2 = j2c;
        if (it < 7){
            int e2 = e + 1;
            int s2 = src[e2], d2 = dst[e2];
            n1c = *reinterpret_cast<const float4*>(g_ni + (size_t)s2*256 + c1);
            n2c = *reinterpret_cast<const float4*>(g_ni + (size_t)s2*256 + c2);
            j1c = *reinterpret_cast<const float4*>(g_nj + (size_t)d2*256 + c1);
            j2c = *reinterpret_cast<const float4*>(g_nj + (size_t)d2*256 + c2);
        }
        float4 f1 = *reinterpret_cast<const float4*>(sFo + el*FOS + c1);
        float4 f2 = *reinterpret_cast<const float4*>(sFo + el*FOS + c2);
        f1.x += be1.x + n1.x + j1.x; f1.y += be1.y + n1.y + j1.y;
        f1.z += be1.z + n1.z + j1.z; f1.w += be1.w + n1.w + j1.w;
        f2.x += be2.x + n2.x + j2.x; f2.y += be2.y + n2.y + j2.y;
        f2.z += be2.z + n2.z + j2.z; f2.w += be2.w + n2.w + j2.w;

        float p1 = lky(f1.x)*at1.x + lky(f1.y)*at1.y + lky(f1.z)*at1.z + lky(f1.w)*at1.w;
        float p2 = lky(f2.x)*at2.x + lky(f2.y)*at2.y + lky(f2.z)*at2.z + lky(f2.w)*at2.w;
        #pragma unroll
        for (int o=8;o>0;o>>=1){
            p1 += __shfl_xor_sync(0xffffffffu, p1, o);
            p2 += __shfl_xor_sync(0xffffffffu, p2, o);
        }
        if (lane == 0){
            g_score[(size_t)e*4 + 0] = p1;
            g_score[(size_t)e*4 + 2] = p2;
        } else if (lane == 16){
            g_score[(size_t)e*4 + 1] = p1;
            g_score[(size_t)e*4 + 3] = p2;
        }

        float4 hm;
        hm.x = f1.x + f2.x; hm.y = f1.y + f2.y; hm.z = f1.z + f2.z; hm.w = f1.w + f2.w;
        hm.x = 0.25f*(hm.x + __shfl_xor_sync(0xffffffffu, hm.x, 16));
        hm.y = 0.25f*(hm.y + __shfl_xor_sync(0xffffffffu, hm.y, 16));
        hm.z = 0.25f*(hm.z + __shfl_xor_sync(0xffffffffu, hm.z, 16));
        hm.w = 0.25f*(hm.w + __shfl_xor_sync(0xffffffffu, hm.w, 16));
        float s1 = hm.x + hm.y + hm.z + hm.w;
        float s2 = hm.x*hm.x + hm.y*hm.y + hm.z*hm.z + hm.w*hm.w;
        #pragma unroll
        for (int o=8;o>0;o>>=1){
            s1 += __shfl_xor_sync(0xffffffffu, s1, o);
            s2 += __shfl_xor_sync(0xffffffffu, s2, o);
        }
        float m   = s1 * 0.015625f;
        float var = s2 * 0.015625f - m*m;
        float inv = rsqrtf(var + 1e-5f);
        if (lane < 16){
            float4 o4;
            o4.x = (hm.x - m)*inv; o4.x = o4.x > 0.f ? o4.x : expm1f(o4.x);
            o4.y = (hm.y - m)*inv; o4.y = o4.y > 0.f ? o4.y : expm1f(o4.y);
            o4.z = (hm.z - m)*inv; o4.z = o4.z > 0.f ? o4.z : expm1f(o4.z);
            o4.w = (hm.w - m)*inv; o4.w = o4.w > 0.f ? o4.w : expm1f(o4.w);
            __nv_bfloat16 h0 = __float2bfloat16(o4.x), h1 = __float2bfloat16(o4.y);
            __nv_bfloat16 h2 = __float2bfloat16(o4.z), h3 = __float2bfloat16(o4.w);
            __nv_bfloat16 l0 = __float2bfloat16(o4.x - __bfloat162float(h0));
            __nv_bfloat16 l1 = __float2bfloat16(o4.y - __bfloat162float(h1));
            __nv_bfloat16 l2 = __float2bfloat16(o4.z - __bfloat162float(h2));
            __nv_bfloat16 l3 = __float2bfloat16(o4.w - __bfloat162float(h3));
            int t = c1;
            __nv_bfloat162* dh = reinterpret_cast<__nv_bfloat162*>(g_fb + (size_t)e*128 + t);
            dh[0] = __nv_bfloat162(h0, h1);
            dh[1] = __nv_bfloat162(h2, h3);
            __nv_bfloat162* dl = reinterpret_cast<__nv_bfloat162*>(g_fb + (size_t)e*128 + 64 + t);
            dl[0] = __nv_bfloat162(l0, l1);
            dl[1] = __nv_bfloat162(l2, l3);
        }
    }
}

// ---------------- small GEMMs ----------------
__global__ __launch_bounds__(256) void sg_init(
    const float* __restrict__ A0, const float* __restrict__ W0, const float* __restrict__ b0,
    const float* __restrict__ A1, const float* __restrict__ W1, const float* __restrict__ b1){
    const int y = blockIdx.y;
    const float* A = y ? A1 : A0;
    const float* W = y ? W1 : W0;
    const float* bias = y ? b1 : b0;
    __nv_bfloat16* out2 = y ? g_fb : g_hb;
    const int rows = y ? NE : NN;
    const int K    = y ? 15 : 65;
    __shared__ float sW[65*64];
    __shared__ float sA[4*65];
    for (int i=threadIdx.x; i<K*64; i+=256) sW[i] = W[i];
    __syncthreads();
    const int col = threadIdx.x & 63;
    const int rl  = threadIdx.x >> 6;
    const float b = bias[col];
    for (int base = blockIdx.x*4; base < rows; base += gridDim.x*4){
        for (int i=threadIdx.x; i<4*K; i+=256){
            int r = i / K, k = i - r*K;
            sA[i] = (base + r < rows) ? A[(size_t)(base+r)*K + k] : 0.f;
        }
        __syncthreads();
        const int row = base + rl;
        if (row < rows){
            float acc = b;
            for (int k=0;k<K;k++) acc += sA[rl*K + k]*sW[k*64 + col];
            __nv_bfloat16 h = __float2bfloat16(acc);
            out2[(size_t)row*128 + col]      = h;
            out2[(size_t)row*128 + 64 + col] = __float2bfloat16(acc - __bfloat162float(h));
        }
        __syncthreads();
    }
}

__global__ __launch_bounds__(256) void sg_final(
    const float* __restrict__ W, const float* __restrict__ bias, float* __restrict__ out){
    __shared__ float sW[64*64];
    __shared__ float sA[4*64];
    for (int i=threadIdx.x; i<64*64; i+=256) sW[i] = W[i];
    __syncthreads();
    const int col = threadIdx.x & 63;
    const int rl  = threadIdx.x >> 6;
    const float b = bias[col];
    for (int base = blockIdx.x*4; base < NN; base += gridDim.x*4){
        for (int i=threadIdx.x; i<4*64; i+=256){
            int r = i >> 6, k = i & 63;
            sA[i] = (base + r < NN) ? g_h[(base+r)*64 + k] : 0.f;
        }
        __syncthreads();
        const int row = base + rl;
        if (row < NN){
            float acc = b;
            for (int k=0;k<64;k++) acc += sA[rl*64 + k]*sW[k*64 + col];
            out[row*64 + col] = acc;
        }
        __syncthreads();
    }
}

// ---------------- fused softmax + aggregate + mean-heads + inorm + elu ----------------
__global__ __launch_bounds__(64) void aggregate(const int* __restrict__ src){
    const int n = blockIdx.x, t = threadIdx.x;
    const int w = t >> 5, lane = t & 31;
    const int beg = g_rowptr[n], end = g_rowptr[n+1];
    const float4* SC = reinterpret_cast<const float4*>(g_score);

    float4 mx = make_float4(-3.4e38f,-3.4e38f,-3.4e38f,-3.4e38f);
    for (int i=beg+t; i<end; i+=64){
        float4 s = SC[g_eidx[i]];
        mx.x = fmaxf(mx.x, s.x); mx.y = fmaxf(mx.y, s.y);
        mx.z = fmaxf(mx.z, s.z); mx.w = fmaxf(mx.w, s.w);
    }
    #pragma unroll
    for (int o=16;o>0;o>>=1){
        mx.x = fmaxf(mx.x, __shfl_down_sync(0xffffffffu, mx.x, o));
        mx.y = fmaxf(mx.y, __shfl_down_sync(0xffffffffu, mx.y, o));
        mx.z = fmaxf(mx.z, __shfl_down_sync(0xffffffffu, mx.z, o));
        mx.w = fmaxf(mx.w, __shfl_down_sync(0xffffffffu, mx.w, o));
    }
    __shared__ float4 sM[2];
    __shared__ float4 sD[2];
    if (lane == 0) sM[w] = mx;
    __syncthreads();
    mx.x = fmaxf(sM[0].x, sM[1].x); mx.y = fmaxf(sM[0].y, sM[1].y);
    mx.z = fmaxf(sM[0].z, sM[1].z); mx.w = fmaxf(sM[0].w, sM[1].w);

    float4 dn = make_float4(0.f,0.f,0.f,0.f);
    for (int i=beg+t; i<end; i+=64){
        float4 s = SC[g_eidx[i]];
        dn.x += __expf(s.x-mx.x); dn.y += __expf(s.y-mx.y);
        dn.z += __expf(s.z-mx.z); dn.w += __expf(s.w-mx.w);
    }
    #pragma unroll
    for (int o=16;o>0;o>>=1){
        dn.x += __shfl_down_sync(0xffffffffu, dn.x, o);
        dn.y += __shfl_down_sync(0xffffffffu, dn.y, o);
        dn.z += __shfl_down_sync(0xffffffffu, dn.z, o);
        dn.w += __shfl_down_sync(0xffffffffu, dn.w, o);
    }
    if (lane == 0) sD[w] = dn;
    __syncthreads();
    dn.x = sD[0].x + sD[1].x; dn.y = sD[0].y + sD[1].y;
    dn.z = sD[0].z + sD[1].z; dn.w = sD[0].w + sD[1].w;

    const int q = t >> 4;
    const float mq = (q==0)?mx.x:(q==1)?mx.y:(q==2)?mx.z:mx.w;
    const float dq = (q==0)?dn.x:(q==1)?dn.y:(q==2)?dn.z:dn.w;
    const float rq = (end > beg) ? 1.0f/dq : 0.f;
    float4 acc = make_float4(0.f,0.f,0.f,0.f);
    for (int i=beg; i<end; i++){
        int e = g_eidx[i];
        float a = __expf(g_score[(size_t)e*4 + q] - mq) * rq;
        float4 hp = reinterpret_cast<const float4*>(g_hp)[src[e]*64 + t];
        acc.x += hp.x*a; acc.y += hp.y*a; acc.z += hp.z*a; acc.w += hp.w*a;
    }

    __shared__ float sAcc[256];
    reinterpret_cast<float4*>(sAcc)[t] = acc;
    __syncthreads();
    float v = 0.25f*(sAcc[t] + sAcc[t+64] + sAcc[t+128] + sAcc[t+192]);
    float s1 = v, s2 = v*v;
    #pragma unroll
    for (int o=16;o>0;o>>=1){
        s1 += __shfl_down_sync(0xffffffffu, s1, o);
        s2 += __shfl_down_sync(0xffffffffu, s2, o);
    }
    __shared__ float sS[4];
    if (lane == 0){ sS[w] = s1; sS[2+w] = s2; }
    __syncthreads();
    float m   = (sS[0]+sS[1]) * 0.015625f;
    float var = (sS[2]+sS[3]) * 0.015625f - m*m;
    float o = (v - m) * rsqrtf(var + 1e-5f);
    o = o > 0.f ? o : expm1f(o);
    g_h[n*64 + t] = o;
    __nv_bfloat16 hi = __float2bfloat16(o);
    g_hb[(size_t)n*128 + t]      = hi;
    g_hb[(size_t)n*128 + 64 + t] = __float2bfloat16(o - __bfloat162float(hi));
}

// ---------------- host ----------------
extern "C" void kernel_launch(void* const* d_in, const int* in_sizes, int n_in,
                              void* d_out, int out_size){
    (void)in_sizes; (void)n_in; (void)out_size;
    const float* x      = (const float*)d_in[0];
    const float* efeat  = (const float*)d_in[1];
    const int*   src    = (const int*)  d_in[2];
    const int*   dst    = (const int*)  d_in[3];
    const float* Wn0    = (const float*)d_in[4];
    const float* bn0    = (const float*)d_in[5];
    const float* We0    = (const float*)d_in[6];
    const float* be0    = (const float*)d_in[7];
    const float* Wnode  = (const float*)d_in[8];
    const float* bnode  = (const float*)d_in[9];
    const float* Wni    = (const float*)d_in[10];
    const float* Wnj    = (const float*)d_in[11];
    const float* Wfij   = (const float*)d_in[12];
    const float* attn   = (const float*)d_in[13];
    const float* bias_e = (const float*)d_in[14];
    const float* Wf     = (const float*)d_in[15];
    const float* bf     = (const float*)d_in[16];

    float *p_ni, *p_nj, *p_hp;
    __nv_bfloat16 *p_hb, *p_wb;
    int* p_cur;
    cudaGetSymbolAddress((void**)&p_ni, g_ni);
    cudaGetSymbolAddress((void**)&p_nj, g_nj);
    cudaGetSymbolAddress((void**)&p_hp, g_hp);
    cudaGetSymbolAddress((void**)&p_hb, g_hb);
    cudaGetSymbolAddress((void**)&p_wb, g_wbuf);
    cudaGetSymbolAddress((void**)&p_cur, g_cur);

    cudaFuncSetAttribute(mma_gemm,  cudaFuncAttributeMaxDynamicSharedMemorySize, MMA_SMEM);
    cudaFuncSetAttribute(edge_gemm, cudaFuncAttributeMaxDynamicSharedMemorySize, EG_SMEM);

    sg_init<<<dim3(8192, 2), 256>>>(x, Wn0, bn0, efeat, We0, be0);        // 0
    k_wconv_all<<<dim3(192, 8), 256>>>(Wni, Wnj, Wnode, Wfij);            // 1
    mma_gemm<<<dim3(157, 6), 256, MMA_SMEM>>>(
        p_hb, p_wb, bnode, p_ni, p_nj, p_hp, NN);                         // 2
    edge_gemm<<<3125, 256, EG_SMEM>>>(
        p_wb + (size_t)3*49152, src, dst, bias_e, attn);                  // 3  <-- profiled
    cudaMemsetAsync(p_cur, 0, NN*sizeof(int));
    k_count<<<(NE+255)/256, 256>>>(dst);
    k_scan<<<1, 1024>>>();
    k_scatter<<<(NE+255)/256, 256>>>(dst);
    aggregate<<<NN, 64>>>(src);

    mma_gemm<<<dim3(157, 6), 256, MMA_SMEM>>>(
        p_hb, p_wb + (size_t)4*49152, bnode + 256, p_ni, p_nj, p_hp, NN);
    edge_gemm<<<3125, 256, EG_SMEM>>>(
        p_wb + (size_t)7*49152, src, dst, bias_e + 256, attn + 256);
    aggregate<<<NN, 64>>>(src);

    sg_final<<<5000, 256>>>(Wf, bf, (float*)d_out);
}